// round 15
// baseline (speedup 1.0000x reference)
#include <cuda_runtime.h>
#include <cuda_fp16.h>
#include <mma.h>

using namespace nvcuda;

#define N_NODES 100000
#define N_EDGES 1600000
#define F 128
#define NB_GEMM 1563           // ceil(100000 / 64)
#define NB_SPMM 1480           // spmm blocks (grid-stride, 8 warps each)
#define BN_EPS 1e-5f

#define XS_LD 136              // padded x-tile lda (halfs)
#define ST_LD 20               // staging pad (floats)
#define SMEM_W_HALFS  (F * F)                  // 16384 halfs = 32 KB
#define SMEM_XS_HALFS (64 * XS_LD)             // 8704 halfs  = 17 KB
#define SMEM_GEMM_BYTES ((SMEM_W_HALFS + SMEM_XS_HALFS) * 2 + 4 * 16 * ST_LD * 4)

// -------- scratch (static device allocations are allowed) --------
__device__ int      g_row_ptr[N_NODES + 1];
__device__ __half   g_wh[F * F];                   // W in fp16 (32 KB)
__device__ __half   g_y[(size_t)N_NODES * F];      // y = x @ W^T fp16 (25.6 MB)
__device__ float    g_psum[(size_t)NB_SPMM * F];   // [block][feature], coalesced
__device__ float    g_psq [(size_t)NB_SPMM * F];
__device__ float    g_scale[F];
__device__ float    g_shift[F];

// ---------------- kernel 0a: row_ptr via boundary scatter ----------------
__global__ void k_rowptr(const int* __restrict__ adj_row) {
    int e = blockIdx.x * blockDim.x + threadIdx.x;
    if (e >= N_EDGES) return;
    int r1 = __ldg(&adj_row[e]);
    if (e == 0) {
        for (int r = 0; r <= r1; r++) g_row_ptr[r] = 0;
    }
    int r2 = (e + 1 < N_EDGES) ? __ldg(&adj_row[e + 1]) : N_NODES;
    for (int r = r1 + 1; r <= r2; r++) g_row_ptr[r] = e + 1;
}

// ---------------- kernel 0b: W -> fp16 ----------------
__global__ void k_wh(const float* __restrict__ fc_w) {
    int i = (blockIdx.x * blockDim.x + threadIdx.x) * 4;
    if (i >= F * F) return;
    float4 v = *reinterpret_cast<const float4*>(fc_w + i);
    __half2* dst = reinterpret_cast<__half2*>(g_wh + i);
    dst[0] = __floats2half2_rn(v.x, v.y);
    dst[1] = __floats2half2_rn(v.z, v.w);
}

// ------------- kernel 1: tensor-core GEMM y = x @ W^T -------------
// 128 threads (4 warps), 64 nodes/block; W staged in smem -> B via LDSM.
__global__ void __launch_bounds__(128)
k_gemm_tc(const float* __restrict__ x) {
    extern __shared__ __half dyn[];
    __half* ws = dyn;                              // 32 KB
    __half* xs = dyn + SMEM_W_HALFS;               // 17 KB
    float*  stage = reinterpret_cast<float*>(xs + SMEM_XS_HALFS);  // 5 KB

    const int t    = threadIdx.x;
    const int warp = t >> 5;
    const int lane = t & 31;
    const int n0   = blockIdx.x * 64;
    const int nv   = min(64, N_NODES - n0);

    // stage W: 2048 uint4 copies by 128 threads
#pragma unroll
    for (int i = 0; i < 16; i++) {
        int idx = i * 128 + t;
        reinterpret_cast<uint4*>(ws)[idx] =
            __ldg(&reinterpret_cast<const uint4*>(g_wh)[idx]);
    }

    // load x tile (fp32) -> smem fp16, rows >= nv zero-filled
#pragma unroll
    for (int i = 0; i < 16; i++) {
        int idx = i * 128 + t;                     // float4 index 0..2047
        int r = idx >> 5, c4 = idx & 31;
        float4 v = (r < nv)
            ? __ldg(&reinterpret_cast<const float4*>(x)[(size_t)(n0 + r) * 32 + c4])
            : make_float4(0.f, 0.f, 0.f, 0.f);
        __half2* dst = reinterpret_cast<__half2*>(xs + r * XS_LD + c4 * 4);
        dst[0] = __floats2half2_rn(v.x, v.y);
        dst[1] = __floats2half2_rn(v.z, v.w);
    }
    __syncthreads();

    wmma::fragment<wmma::matrix_a, 16, 16, 16, __half, wmma::row_major> a[8];
#pragma unroll
    for (int k = 0; k < 8; k++)
        wmma::load_matrix_sync(a[k], xs + warp * 16 * XS_LD + k * 16, XS_LD);

    float* st = stage + warp * 16 * ST_LD;
    __half2* y2 = reinterpret_cast<__half2*>(g_y);

#pragma unroll
    for (int nt = 0; nt < 8; nt++) {
        wmma::fragment<wmma::accumulator, 16, 16, 16, float> c;
        wmma::fill_fragment(c, 0.0f);
#pragma unroll
        for (int k = 0; k < 8; k++) {
            wmma::fragment<wmma::matrix_b, 16, 16, 16, __half, wmma::col_major> b;
            wmma::load_matrix_sync(b, ws + nt * 16 * F + k * 16, F);
            wmma::mma_sync(c, a[k], b, c);
        }
        wmma::store_matrix_sync(st, c, ST_LD, wmma::mem_row_major);
        __syncwarp();
#pragma unroll
        for (int i = 0; i < 4; i++) {
            int e  = i * 32 + lane;                // 128 half2 in tile
            int r  = e >> 3, c2 = e & 7;
            int gr = warp * 16 + r;
            if (gr < nv) {
                float2 v = *reinterpret_cast<const float2*>(st + r * ST_LD + c2 * 2);
                y2[(size_t)(n0 + gr) * 64 + nt * 8 + c2] = __floats2half2_rn(v.x, v.y);
            }
        }
        __syncwarp();
    }
}

// ------- kernel 2: SpMM over y (fp16) + bias -> d_out -------
// grid-stride warp-per-node; lane owns features [4*lane, 4*lane+4).
// launch_bounds(256,3): ~85-reg budget so the 8 gathers stay batched (MLP).
__device__ __forceinline__ void edge_acc(float4& acc, int c, float v,
                                         const uint2* yv, int lane) {
    uint2 raw = __ldg(&yv[(size_t)c * 32 + lane]);
    float2 f0 = __half22float2(*reinterpret_cast<__half2*>(&raw.x));
    float2 f1 = __half22float2(*reinterpret_cast<__half2*>(&raw.y));
    acc.x += v * f0.x; acc.y += v * f0.y;
    acc.z += v * f1.x; acc.w += v * f1.y;
}

__global__ void __launch_bounds__(256, 3)
k_spmm(const int*   __restrict__ adj_col,
       const float* __restrict__ adj_val,
       const float* __restrict__ fc_b,
       float*       __restrict__ h_out) {
    __shared__ float4 red_s[8][32];
    __shared__ float4 red_q[8][32];

    const int wid  = threadIdx.x >> 5;
    const int lane = threadIdx.x & 31;
    const int gw   = blockIdx.x * 8 + wid;
    const int nw   = gridDim.x * 8;
    const uint2* yv = reinterpret_cast<const uint2*>(g_y);
    const float4 bb = __ldg(&reinterpret_cast<const float4*>(fc_b)[lane]);

    float4 bs = make_float4(0.f, 0.f, 0.f, 0.f);
    float4 bq = make_float4(0.f, 0.f, 0.f, 0.f);

    for (int n = gw; n < N_NODES; n += nw) {
        const int s = g_row_ptr[n];
        const int e = g_row_ptr[n + 1];

        float4 acc = make_float4(0.f, 0.f, 0.f, 0.f);
        int k = s;

        // align k to 4 for vector loads
        int kal = (s + 3) & ~3; if (kal > e) kal = e;
        for (; k < kal; k++)
            edge_acc(acc, __ldg(&adj_col[k]), __ldg(&adj_val[k]), yv, lane);

        // 8-edge chunks: 4 uniform vector loads + 8 batched gathers
        for (; k + 8 <= e; k += 8) {
            int4   ca = __ldg(reinterpret_cast<const int4*>(adj_col + k));
            int4   cb = __ldg(reinterpret_cast<const int4*>(adj_col + k + 4));
            float4 va = __ldg(reinterpret_cast<const float4*>(adj_val + k));
            float4 vb = __ldg(reinterpret_cast<const float4*>(adj_val + k + 4));
            uint2 r0 = __ldg(&yv[(size_t)ca.x * 32 + lane]);
            uint2 r1 = __ldg(&yv[(size_t)ca.y * 32 + lane]);
            uint2 r2 = __ldg(&yv[(size_t)ca.z * 32 + lane]);
            uint2 r3 = __ldg(&yv[(size_t)ca.w * 32 + lane]);
            uint2 r4 = __ldg(&yv[(size_t)cb.x * 32 + lane]);
            uint2 r5 = __ldg(&yv[(size_t)cb.y * 32 + lane]);
            uint2 r6 = __ldg(&yv[(size_t)cb.z * 32 + lane]);
            uint2 r7 = __ldg(&yv[(size_t)cb.w * 32 + lane]);
#define CONSUME(raw, v)                                                        \
            {                                                                  \
                float2 f0 = __half22float2(*reinterpret_cast<__half2*>(&raw.x));\
                float2 f1 = __half22float2(*reinterpret_cast<__half2*>(&raw.y));\
                acc.x += (v) * f0.x; acc.y += (v) * f0.y;                      \
                acc.z += (v) * f1.x; acc.w += (v) * f1.y;                      \
            }
            CONSUME(r0, va.x) CONSUME(r1, va.y) CONSUME(r2, va.z) CONSUME(r3, va.w)
            CONSUME(r4, vb.x) CONSUME(r5, vb.y) CONSUME(r6, vb.z) CONSUME(r7, vb.w)
        }
        // 4-edge chunk
        if (k + 4 <= e) {
            int4   ca = __ldg(reinterpret_cast<const int4*>(adj_col + k));
            float4 va = __ldg(reinterpret_cast<const float4*>(adj_val + k));
            uint2 r0 = __ldg(&yv[(size_t)ca.x * 32 + lane]);
            uint2 r1 = __ldg(&yv[(size_t)ca.y * 32 + lane]);
            uint2 r2 = __ldg(&yv[(size_t)ca.z * 32 + lane]);
            uint2 r3 = __ldg(&yv[(size_t)ca.w * 32 + lane]);
            CONSUME(r0, va.x) CONSUME(r1, va.y) CONSUME(r2, va.z) CONSUME(r3, va.w)
            k += 4;
        }
#undef CONSUME
        // scalar tail
        for (; k < e; k++)
            edge_acc(acc, __ldg(&adj_col[k]), __ldg(&adj_val[k]), yv, lane);

        acc.x += bb.x; acc.y += bb.y; acc.z += bb.z; acc.w += bb.w;
        reinterpret_cast<float4*>(h_out)[(size_t)n * 32 + lane] = acc;

        bs.x += acc.x; bs.y += acc.y; bs.z += acc.z; bs.w += acc.w;
        bq.x += acc.x * acc.x; bq.y += acc.y * acc.y;
        bq.z += acc.z * acc.z; bq.w += acc.w * acc.w;
    }

    red_s[wid][lane] = bs;
    red_q[wid][lane] = bq;
    __syncthreads();
    if (wid == 0) {
        float4 s4 = red_s[0][lane], q4 = red_q[0][lane];
#pragma unroll
        for (int i = 1; i < 8; i++) {
            float4 a = red_s[i][lane], b = red_q[i][lane];
            s4.x += a.x; s4.y += a.y; s4.z += a.z; s4.w += a.w;
            q4.x += b.x; q4.y += b.y; q4.z += b.z; q4.w += b.w;
        }
        reinterpret_cast<float4*>(g_psum)[blockIdx.x * 32 + lane] = s4;
        reinterpret_cast<float4*>(g_psq )[blockIdx.x * 32 + lane] = q4;
    }
}

// ---------------- kernel 3: finalize BN stats ----------------
__global__ void __launch_bounds__(256)
k_stats(const float* __restrict__ bn_gamma,
        const float* __restrict__ bn_beta) {
    __shared__ float ss[8], qq[8];
    const int o = blockIdx.x;
    const int t = threadIdx.x;

    float s = 0.f, q = 0.f;
    for (int b = t; b < NB_SPMM; b += 256) {
        s += __ldg(&g_psum[(size_t)b * F + o]);
        q += __ldg(&g_psq [(size_t)b * F + o]);
    }
#pragma unroll
    for (int off = 16; off; off >>= 1) {
        s += __shfl_down_sync(0xffffffffu, s, off);
        q += __shfl_down_sync(0xffffffffu, q, off);
    }
    if ((t & 31) == 0) { ss[t >> 5] = s; qq[t >> 5] = q; }
    __syncthreads();
    if (t == 0) {
        s = 0.f; q = 0.f;
#pragma unroll
        for (int i = 0; i < 8; i++) { s += ss[i]; q += qq[i]; }
        const float inv_n = 1.0f / (float)N_NODES;
        float mean = s * inv_n;
        float var  = q * inv_n - mean * mean;
        float isd  = rsqrtf(var + BN_EPS);
        float sc   = __ldg(&bn_gamma[o]) * isd;
        g_scale[o] = sc;
        g_shift[o] = __ldg(&bn_beta[o]) - mean * sc;
    }
}

// ---------------- kernel 4: in-place normalize ----------------
__global__ void k_norm(float* __restrict__ h) {
    const size_t total = (size_t)N_NODES * F;
    size_t i = ((size_t)blockIdx.x * blockDim.x + threadIdx.x) * 4;
    if (i >= total) return;
    int o = (int)(i & (F - 1));
    float4 v  = *reinterpret_cast<float4*>(h + i);
    float4 sc = *reinterpret_cast<const float4*>(g_scale + o);
    float4 sh = *reinterpret_cast<const float4*>(g_shift + o);
    v.x = v.x * sc.x + sh.x;
    v.y = v.y * sc.y + sh.y;
    v.z = v.z * sc.z + sh.z;
    v.w = v.w * sc.w + sh.w;
    *reinterpret_cast<float4*>(h + i) = v;
}

// ---------------- launch (single stream) ----------------
extern "C" void kernel_launch(void* const* d_in, const int* in_sizes, int n_in,
                              void* d_out, int out_size) {
    const float* x        = (const float*)d_in[0];
    const int*   adj_row  = (const int*)  d_in[1];
    const int*   adj_col  = (const int*)  d_in[2];
    const float* adj_val  = (const float*)d_in[3];
    const float* fc_w     = (const float*)d_in[4];
    const float* fc_b     = (const float*)d_in[5];
    const float* bn_gamma = (const float*)d_in[6];
    const float* bn_beta  = (const float*)d_in[7];
    float* out = (float*)d_out;

    cudaFuncSetAttribute(k_gemm_tc,
                         cudaFuncAttributeMaxDynamicSharedMemorySize,
                         SMEM_GEMM_BYTES);

    k_rowptr<<<(N_EDGES + 255) / 256, 256>>>(adj_row);
    k_wh<<<(F * F / 4 + 255) / 256, 256>>>(fc_w);
    k_gemm_tc<<<NB_GEMM, 128, SMEM_GEMM_BYTES>>>(x);
    k_spmm<<<NB_SPMM, 256>>>(adj_col, adj_val, fc_b, out);
    k_stats<<<F, 256>>>(bn_gamma, bn_beta);
    k_norm<<<(N_NODES * F / 4 + 255) / 256, 256>>>(out);
}

// round 16
// speedup vs baseline: 1.2324x; 1.2324x over previous
#include <cuda_runtime.h>
#include <cuda_fp16.h>
#include <mma.h>

using namespace nvcuda;

#define N_NODES 100000
#define N_EDGES 1600000
#define F 128
#define NB_GEMM 782            // ceil(100000 / 128); 100000-781*128=32 (mult of 16)
#define NB_SPMM 1480           // spmm blocks (grid-stride, 8 warps each)
#define BN_EPS 1e-5f

#define XS_LD 136              // padded x-tile lda (halfs)
#define ST_LD 20               // staging pad (floats)

// -------- scratch (static device allocations are allowed) --------
__device__ int      g_row_ptr[N_NODES + 1];
__device__ __half   g_wh[F * F];                   // W in fp16 (32 KB)
__device__ __half   g_y[(size_t)N_NODES * F];      // y = x @ W^T fp16 (25.6 MB)
__device__ __half   g_h[(size_t)N_NODES * F];      // h pre-BN in fp16 (25.6 MB)
__device__ float    g_psum[(size_t)NB_SPMM * F];   // [block][feature], coalesced
__device__ float    g_psq [(size_t)NB_SPMM * F];
__device__ float    g_scale[F];
__device__ float    g_shift[F];

// ---------------- kernel 0a: row_ptr via boundary scatter ----------------
__global__ void k_rowptr(const int* __restrict__ adj_row) {
    int e = blockIdx.x * blockDim.x + threadIdx.x;
    if (e >= N_EDGES) return;
    int r1 = __ldg(&adj_row[e]);
    if (e == 0) {
        for (int r = 0; r <= r1; r++) g_row_ptr[r] = 0;
    }
    int r2 = (e + 1 < N_EDGES) ? __ldg(&adj_row[e + 1]) : N_NODES;
    for (int r = r1 + 1; r <= r2; r++) g_row_ptr[r] = e + 1;
}

// ---------------- kernel 0b: W -> fp16 ----------------
__global__ void k_wh(const float* __restrict__ fc_w) {
    int i = (blockIdx.x * blockDim.x + threadIdx.x) * 4;
    if (i >= F * F) return;
    float4 v = *reinterpret_cast<const float4*>(fc_w + i);
    __half2* dst = reinterpret_cast<__half2*>(g_wh + i);
    dst[0] = __floats2half2_rn(v.x, v.y);
    dst[1] = __floats2half2_rn(v.z, v.w);
}

// ------------- kernel 1: tensor-core GEMM y = x @ W^T -------------
// 128 threads (4 warps), 128 nodes/block; warp owns M=32 (2 row tiles)
// so each global-W b-fragment load feeds TWO MMAs.
__global__ void __launch_bounds__(128)
k_gemm_tc(const float* __restrict__ x) {
    __shared__ __half xs[128 * XS_LD];         // 34.8 KB
    __shared__ float  stage[4][16 * ST_LD];    // 5.1 KB per-warp staging

    const int t    = threadIdx.x;
    const int warp = t >> 5;
    const int lane = t & 31;
    const int n0   = blockIdx.x * 128;
    const int nv   = min(128, N_NODES - n0);   // always multiple of 16

    // load x tile (fp32) -> smem fp16, rows >= nv zero-filled
#pragma unroll
    for (int i = 0; i < 32; i++) {
        int idx = i * 128 + t;                 // float4 index 0..4095
        int r = idx >> 5, c4 = idx & 31;
        float4 v = (r < nv)
            ? __ldg(&reinterpret_cast<const float4*>(x)[(size_t)(n0 + r) * 32 + c4])
            : make_float4(0.f, 0.f, 0.f, 0.f);
        __half2* dst = reinterpret_cast<__half2*>(xs + r * XS_LD + c4 * 4);
        dst[0] = __floats2half2_rn(v.x, v.y);
        dst[1] = __floats2half2_rn(v.z, v.w);
    }
    __syncthreads();

    // 16 a-fragments: 2 row tiles x 8 k tiles
    wmma::fragment<wmma::matrix_a, 16, 16, 16, __half, wmma::row_major> a[16];
#pragma unroll
    for (int rt = 0; rt < 2; rt++)
#pragma unroll
        for (int k = 0; k < 8; k++)
            wmma::load_matrix_sync(a[rt * 8 + k],
                                   xs + (warp * 32 + rt * 16) * XS_LD + k * 16,
                                   XS_LD);

    float* st = stage[warp];
    __half2* y2 = reinterpret_cast<__half2*>(g_y);

#pragma unroll
    for (int nt = 0; nt < 8; nt++) {
        wmma::fragment<wmma::accumulator, 16, 16, 16, float> c0, c1;
        wmma::fill_fragment(c0, 0.0f);
        wmma::fill_fragment(c1, 0.0f);
#pragma unroll
        for (int k = 0; k < 8; k++) {
            wmma::fragment<wmma::matrix_b, 16, 16, 16, __half, wmma::col_major> b;
            wmma::load_matrix_sync(b, g_wh + nt * 16 * F + k * 16, F);
            wmma::mma_sync(c0, a[k],     b, c0);
            wmma::mma_sync(c1, a[8 + k], b, c1);
        }
#pragma unroll
        for (int rt = 0; rt < 2; rt++) {
            wmma::store_matrix_sync(st, rt ? c1 : c0, ST_LD, wmma::mem_row_major);
            __syncwarp();
#pragma unroll
            for (int i = 0; i < 4; i++) {
                int e  = i * 32 + lane;        // 128 half2 in 16x16 tile
                int r  = e >> 3, c2 = e & 7;
                int gr = warp * 32 + rt * 16 + r;
                if (gr < nv) {
                    float2 v = *reinterpret_cast<const float2*>(st + r * ST_LD + c2 * 2);
                    y2[(size_t)(n0 + gr) * 64 + nt * 8 + c2] = __floats2half2_rn(v.x, v.y);
                }
            }
            __syncwarp();
        }
    }
}

// ------- kernel 2: SpMM over y (fp16) + bias -> h (fp16), fp32 BN partials -------
// grid-stride warp-per-node; lane owns features [4*lane, 4*lane+4).
__device__ __forceinline__ void edge_acc(float4& acc, int c, float v,
                                         const uint2* yv, int lane) {
    uint2 raw = __ldg(&yv[(size_t)c * 32 + lane]);
    float2 f0 = __half22float2(*reinterpret_cast<__half2*>(&raw.x));
    float2 f1 = __half22float2(*reinterpret_cast<__half2*>(&raw.y));
    acc.x += v * f0.x; acc.y += v * f0.y;
    acc.z += v * f1.x; acc.w += v * f1.y;
}

__global__ void __launch_bounds__(256)
k_spmm(const int*   __restrict__ adj_col,
       const float* __restrict__ adj_val,
       const float* __restrict__ fc_b) {
    __shared__ float4 red_s[8][32];
    __shared__ float4 red_q[8][32];

    const int wid  = threadIdx.x >> 5;
    const int lane = threadIdx.x & 31;
    const int gw   = blockIdx.x * 8 + wid;
    const int nw   = gridDim.x * 8;
    const uint2* yv = reinterpret_cast<const uint2*>(g_y);
    const float4 bb = __ldg(&reinterpret_cast<const float4*>(fc_b)[lane]);

    float4 bs = make_float4(0.f, 0.f, 0.f, 0.f);
    float4 bq = make_float4(0.f, 0.f, 0.f, 0.f);

    for (int n = gw; n < N_NODES; n += nw) {
        const int s = g_row_ptr[n];
        const int e = g_row_ptr[n + 1];

        float4 acc = make_float4(0.f, 0.f, 0.f, 0.f);
        int k = s;

        // align k to 4 for vector loads
        int kal = (s + 3) & ~3; if (kal > e) kal = e;
        for (; k < kal; k++)
            edge_acc(acc, __ldg(&adj_col[k]), __ldg(&adj_val[k]), yv, lane);

        // 8-edge chunks: 4 uniform vector loads + 8 batched gathers
        for (; k + 8 <= e; k += 8) {
            int4   ca = __ldg(reinterpret_cast<const int4*>(adj_col + k));
            int4   cb = __ldg(reinterpret_cast<const int4*>(adj_col + k + 4));
            float4 va = __ldg(reinterpret_cast<const float4*>(adj_val + k));
            float4 vb = __ldg(reinterpret_cast<const float4*>(adj_val + k + 4));
            uint2 r0 = __ldg(&yv[(size_t)ca.x * 32 + lane]);
            uint2 r1 = __ldg(&yv[(size_t)ca.y * 32 + lane]);
            uint2 r2 = __ldg(&yv[(size_t)ca.z * 32 + lane]);
            uint2 r3 = __ldg(&yv[(size_t)ca.w * 32 + lane]);
            uint2 r4 = __ldg(&yv[(size_t)cb.x * 32 + lane]);
            uint2 r5 = __ldg(&yv[(size_t)cb.y * 32 + lane]);
            uint2 r6 = __ldg(&yv[(size_t)cb.z * 32 + lane]);
            uint2 r7 = __ldg(&yv[(size_t)cb.w * 32 + lane]);
#define CONSUME(raw, v)                                                        \
            {                                                                  \
                float2 f0 = __half22float2(*reinterpret_cast<__half2*>(&raw.x));\
                float2 f1 = __half22float2(*reinterpret_cast<__half2*>(&raw.y));\
                acc.x += (v) * f0.x; acc.y += (v) * f0.y;                      \
                acc.z += (v) * f1.x; acc.w += (v) * f1.y;                      \
            }
            CONSUME(r0, va.x) CONSUME(r1, va.y) CONSUME(r2, va.z) CONSUME(r3, va.w)
            CONSUME(r4, vb.x) CONSUME(r5, vb.y) CONSUME(r6, vb.z) CONSUME(r7, vb.w)
        }
        // 4-edge chunk
        if (k + 4 <= e) {
            int4   ca = __ldg(reinterpret_cast<const int4*>(adj_col + k));
            float4 va = __ldg(reinterpret_cast<const float4*>(adj_val + k));
            uint2 r0 = __ldg(&yv[(size_t)ca.x * 32 + lane]);
            uint2 r1 = __ldg(&yv[(size_t)ca.y * 32 + lane]);
            uint2 r2 = __ldg(&yv[(size_t)ca.z * 32 + lane]);
            uint2 r3 = __ldg(&yv[(size_t)ca.w * 32 + lane]);
            CONSUME(r0, va.x) CONSUME(r1, va.y) CONSUME(r2, va.z) CONSUME(r3, va.w)
            k += 4;
        }
#undef CONSUME
        // scalar tail
        for (; k < e; k++)
            edge_acc(acc, __ldg(&adj_col[k]), __ldg(&adj_val[k]), yv, lane);

        acc.x += bb.x; acc.y += bb.y; acc.z += bb.z; acc.w += bb.w;

        // store h in fp16 (halves k_norm's read traffic)
        uint2 hp;
        __half2 h0 = __floats2half2_rn(acc.x, acc.y);
        __half2 h1 = __floats2half2_rn(acc.z, acc.w);
        hp.x = *reinterpret_cast<unsigned*>(&h0);
        hp.y = *reinterpret_cast<unsigned*>(&h1);
        reinterpret_cast<uint2*>(g_h)[(size_t)n * 32 + lane] = hp;

        bs.x += acc.x; bs.y += acc.y; bs.z += acc.z; bs.w += acc.w;
        bq.x += acc.x * acc.x; bq.y += acc.y * acc.y;
        bq.z += acc.z * acc.z; bq.w += acc.w * acc.w;
    }

    red_s[wid][lane] = bs;
    red_q[wid][lane] = bq;
    __syncthreads();
    if (wid == 0) {
        float4 s4 = red_s[0][lane], q4 = red_q[0][lane];
#pragma unroll
        for (int i = 1; i < 8; i++) {
            float4 a = red_s[i][lane], b = red_q[i][lane];
            s4.x += a.x; s4.y += a.y; s4.z += a.z; s4.w += a.w;
            q4.x += b.x; q4.y += b.y; q4.z += b.z; q4.w += b.w;
        }
        reinterpret_cast<float4*>(g_psum)[blockIdx.x * 32 + lane] = s4;
        reinterpret_cast<float4*>(g_psq )[blockIdx.x * 32 + lane] = q4;
    }
}

// ---------------- kernel 3: finalize BN stats ----------------
__global__ void __launch_bounds__(256)
k_stats(const float* __restrict__ bn_gamma,
        const float* __restrict__ bn_beta) {
    __shared__ float ss[8], qq[8];
    const int o = blockIdx.x;
    const int t = threadIdx.x;

    float s = 0.f, q = 0.f;
    for (int b = t; b < NB_SPMM; b += 256) {
        s += __ldg(&g_psum[(size_t)b * F + o]);
        q += __ldg(&g_psq [(size_t)b * F + o]);
    }
#pragma unroll
    for (int off = 16; off; off >>= 1) {
        s += __shfl_down_sync(0xffffffffu, s, off);
        q += __shfl_down_sync(0xffffffffu, q, off);
    }
    if ((t & 31) == 0) { ss[t >> 5] = s; qq[t >> 5] = q; }
    __syncthreads();
    if (t == 0) {
        s = 0.f; q = 0.f;
#pragma unroll
        for (int i = 0; i < 8; i++) { s += ss[i]; q += qq[i]; }
        const float inv_n = 1.0f / (float)N_NODES;
        float mean = s * inv_n;
        float var  = q * inv_n - mean * mean;
        float isd  = rsqrtf(var + BN_EPS);
        float sc   = __ldg(&bn_gamma[o]) * isd;
        g_scale[o] = sc;
        g_shift[o] = __ldg(&bn_beta[o]) - mean * sc;
    }
}

// ---------------- kernel 4: normalize fp16 h -> fp32 out ----------------
__global__ void k_norm(float* __restrict__ out) {
    const size_t total = (size_t)N_NODES * F;
    size_t i = ((size_t)blockIdx.x * blockDim.x + threadIdx.x) * 4;
    if (i >= total) return;
    int o = (int)(i & (F - 1));
    uint2 hp = *reinterpret_cast<const uint2*>(
        reinterpret_cast<const char*>(g_h) + i * 2);
    float2 f0 = __half22float2(*reinterpret_cast<__half2*>(&hp.x));
    float2 f1 = __half22float2(*reinterpret_cast<__half2*>(&hp.y));
    float4 sc = *reinterpret_cast<const float4*>(g_scale + o);
    float4 sh = *reinterpret_cast<const float4*>(g_shift + o);
    float4 v;
    v.x = f0.x * sc.x + sh.x;
    v.y = f0.y * sc.y + sh.y;
    v.z = f1.x * sc.z + sh.z;
    v.w = f1.y * sc.w + sh.w;
    *reinterpret_cast<float4*>(out + i) = v;
}

// ---------------- launch (single stream) ----------------
extern "C" void kernel_launch(void* const* d_in, const int* in_sizes, int n_in,
                              void* d_out, int out_size) {
    const float* x        = (const float*)d_in[0];
    const int*   adj_row  = (const int*)  d_in[1];
    const int*   adj_col  = (const int*)  d_in[2];
    const float* adj_val  = (const float*)d_in[3];
    const float* fc_w     = (const float*)d_in[4];
    const float* fc_b     = (const float*)d_in[5];
    const float* bn_gamma = (const float*)d_in[6];
    const float* bn_beta  = (const float*)d_in[7];
    float* out = (float*)d_out;

    k_rowptr<<<(N_EDGES + 255) / 256, 256>>>(adj_row);
    k_wh<<<(F * F / 4 + 255) / 256, 256>>>(fc_w);
    k_gemm_tc<<<NB_GEMM, 128>>>(x);
    k_spmm<<<NB_SPMM, 256>>>(adj_col, adj_val, fc_b);
    k_stats<<<F, 256>>>(bn_gamma, bn_beta);
    k_norm<<<(N_NODES * F / 4 + 255) / 256, 256>>>(out);
}